// round 12
// baseline (speedup 1.0000x reference)
#include <cuda_runtime.h>
#include <cstdint>

#define N_SRC   100000
#define N_TGT   50000
#define N_EDGES 600000
#define CH      128
#define NREL    7
#define NTYP    4
#define NSEG    11
#define NBINS   (N_TGT * NREL)          // 350000
#define NPART   342                     // ceil(NBINS/1024)

// Fused kernel tiling
#define TILE_M  64
#define ASTR    132                     // A row stride (words): 128 + 4 pad
#define A_BYTES (TILE_M * ASTR * 4)     // 33792 per buffer
#define BSTR    36                      // B row stride (words)
#define B_BYTES (128 * BSTR * 4)        // 18432 per stage
#define ELIST_CAP 1536

#define OFF_A0  0
#define OFF_A1  A_BYTES
#define OFF_B0  (2 * A_BYTES)
#define OFF_B1  (2 * A_BYTES + B_BYTES)
#define OFF_OFS (2 * A_BYTES + 2 * B_BYTES)
#define OFF_TYP (OFF_OFS + 452 * 4)
#define OFF_EL  (OFF_TYP + 64 * 4)
#define SMEM_TOTAL (OFF_EL + ELIST_CAP * 4)   // 112656 bytes -> 2 CTAs/SM

// Scratch (allocation-free rule: __device__ globals)
__device__ uint32_t g_bincnt[NBINS];
__device__ uint32_t g_binofs[NBINS + 1];
__device__ uint32_t g_part[NPART];
__device__ uint32_t g_elist[N_EDGES];
__device__ uint32_t g_wtf32[NSEG * CH * CH];

// ---------------- helpers ----------------
__device__ __forceinline__ uint32_t to_tf32(float x) {
    uint32_t r;
    asm("cvt.rna.tf32.f32 %0, %1;" : "=r"(r) : "f"(x));
    return r;
}
__device__ __forceinline__ uint32_t smem_u32(const void* p) {
    uint32_t a;
    asm("{ .reg .u64 t; cvta.to.shared.u64 t, %1; cvt.u32.u64 %0, t; }" : "=r"(a) : "l"(p));
    return a;
}
__device__ __forceinline__ void cp16(uint32_t dst, const void* src, bool pred) {
    asm volatile("cp.async.ca.shared.global [%0], [%1], 16, %2;"
                 :: "r"(dst), "l"(src), "r"(pred ? 16 : 0) : "memory");
}
#define CP_COMMIT() asm volatile("cp.async.commit_group;" ::: "memory")
#define CP_WAIT(n)  asm volatile("cp.async.wait_group %0;" :: "n"(n) : "memory")
#define BAR_SYNC(id, cnt)   asm volatile("bar.sync %0, %1;"   :: "r"(id), "r"(cnt) : "memory")
#define BAR_ARRIVE(id, cnt) asm volatile("bar.arrive %0, %1;" :: "r"(id), "r"(cnt) : "memory")
#define LDSM_X4(r0, r1, r2, r3, addr) \
    asm volatile("ldmatrix.sync.aligned.m8n8.x4.shared.b16 {%0,%1,%2,%3}, [%4];" \
        : "=r"(r0), "=r"(r1), "=r"(r2), "=r"(r3) : "r"(addr))

__device__ __forceinline__ void mma_tf32(float* c,
    uint32_t a0, uint32_t a1, uint32_t a2, uint32_t a3,
    uint32_t b0, uint32_t b1)
{
    asm volatile(
        "mma.sync.aligned.m16n8k8.row.col.f32.tf32.tf32.f32 "
        "{%0,%1,%2,%3}, {%4,%5,%6,%7}, {%8,%9}, {%0,%1,%2,%3};"
        : "+f"(c[0]), "+f"(c[1]), "+f"(c[2]), "+f"(c[3])
        : "r"(a0), "r"(a1), "r"(a2), "r"(a3), "r"(b0), "r"(b1));
}

// ---------------- CSR build ----------------
__global__ __launch_bounds__(256) void hist_kernel(
    const int* __restrict__ edst, const int* __restrict__ etyp,
    uint32_t* __restrict__ cnt)
{
    int e = blockIdx.x * 256 + threadIdx.x;
    if (e >= N_EDGES) return;
    atomicAdd(&cnt[__ldg(edst + e) * NREL + __ldg(etyp + e)], 1u);
}

__global__ __launch_bounds__(1024) void scanA_kernel(
    const uint32_t* __restrict__ cnt, uint32_t* __restrict__ part)
{
    __shared__ uint32_t s[1024];
    int t = threadIdx.x;
    int i = blockIdx.x * 1024 + t;
    s[t] = (i < NBINS) ? cnt[i] : 0u;
    __syncthreads();
    for (int off = 512; off; off >>= 1) {
        if (t < off) s[t] += s[t + off];
        __syncthreads();
    }
    if (t == 0) part[blockIdx.x] = s[0];
}

// scanC2: per-block exclusive prefix over part[] computed locally (reduction),
// then block-local inclusive scan of cnt -> global exclusive bin offsets.
__global__ __launch_bounds__(1024) void scanC2_kernel(
    const uint32_t* __restrict__ cnt, const uint32_t* __restrict__ part,
    uint32_t* __restrict__ ofs)
{
    __shared__ uint32_t s[1024];
    __shared__ uint32_t sp[1024];
    __shared__ uint32_t blockPrefix;
    int t = threadIdx.x;
    int b = blockIdx.x;
    uint32_t p = 0;
    for (int i = t; i < b; i += 1024) p += part[i];
    sp[t] = p;
    __syncthreads();
    for (int off = 512; off; off >>= 1) {
        if (t < off) sp[t] += sp[t + off];
        __syncthreads();
    }
    if (t == 0) blockPrefix = sp[0];
    int i = b * 1024 + t;
    uint32_t v = (i < NBINS) ? cnt[i] : 0u;
    s[t] = v;
    __syncthreads();
    for (int off = 1; off < 1024; off <<= 1) {
        uint32_t x = (t >= off) ? s[t - off] : 0u;
        __syncthreads();
        s[t] += x;
        __syncthreads();
    }
    if (i < NBINS) ofs[i] = s[t] - v + blockPrefix;
    if (b == 0 && t == 0) ofs[NBINS] = N_EDGES;
}

// fill: consumes bincnt as the cursor (atomicSub); no separate cursor array.
__global__ __launch_bounds__(256) void fill_kernel(
    const int* __restrict__ esrc, const int* __restrict__ edst,
    const int* __restrict__ etyp,
    const uint32_t* __restrict__ ofs, uint32_t* __restrict__ cnt,
    uint32_t* __restrict__ elist)
{
    int e = blockIdx.x * 256 + threadIdx.x;
    if (e >= N_EDGES) return;
    int bin = __ldg(edst + e) * NREL + __ldg(etyp + e);
    uint32_t idx = atomicSub(&cnt[bin], 1u) - 1u;
    elist[ofs[bin] + idx] = (uint32_t)__ldg(esrc + e);
}

// ---------------- weight pre-convert (B in rna tf32: accuracy margin) -----
__global__ __launch_bounds__(256) void prep_weights(
    const float* __restrict__ relw, const float* __restrict__ rootw,
    uint32_t* __restrict__ wt)
{
    int i = blockIdx.x * 256 + threadIdx.x;
    const int NREL4 = NREL * CH * CH / 4;
    const int TOT4  = NSEG * CH * CH / 4;
    if (i >= TOT4) return;
    float4 v = (i < NREL4) ? ((const float4*)relw)[i]
                           : ((const float4*)rootw)[i - NREL4];
    uint4 w;
    w.x = to_tf32(v.x); w.y = to_tf32(v.y);
    w.z = to_tf32(v.z); w.w = to_tf32(v.w);
    ((uint4*)wt)[i] = w;
}

// ---------------- fused warp-specialized aggregate+GEMM ----------------
// Warps 0-3: consumers (MMA, 64x32 warp tile each).  Warps 4-7: producers
// (gather-aggregate relation A tiles with 4-way edge MLP; masked-copy root).
// Named barriers: 1/4 = A buf even/odd ready; 3/5 = A buf even/odd free;
// 2 = consumer-local B staging.
__global__ __launch_bounds__(256, 2) void fused_kernel(
    const float* __restrict__ xs, const float* __restrict__ xt,
    const uint32_t* __restrict__ wt, const float* __restrict__ rootb,
    const int* __restrict__ ttype,
    const uint32_t* __restrict__ binofs, const uint32_t* __restrict__ elist,
    float* __restrict__ out)
{
    extern __shared__ char smc[];
    const uint32_t sb = smem_u32(smc);
    uint32_t* sOfs = (uint32_t*)(smc + OFF_OFS);
    int*      sTyp = (int*)(smc + OFF_TYP);
    uint32_t* sEl  = (uint32_t*)(smc + OFF_EL);

    const int tid = threadIdx.x;
    const int wid = tid >> 5;
    const int lid = tid & 31;
    const int row0 = blockIdx.x * TILE_M;

    for (int i = tid; i < 449; i += 256) {
        int idx = row0 * NREL + i;
        if (idx > NBINS) idx = NBINS;
        sOfs[i] = binofs[idx];
    }
    if (tid < TILE_M) {
        int g = row0 + tid;
        sTyp[tid] = (g < N_TGT) ? ttype[g] : -1;
    }
    __syncthreads();
    const uint32_t e0 = sOfs[0];
    const int nEdge = (int)(sOfs[448] - e0);
    const bool useS = (nEdge <= ELIST_CAP);
    if (useS)
        for (int i = tid; i < nEdge; i += 256) sEl[i] = elist[e0 + i];
    __syncthreads();

    if (wid < 4) {
        // ================= consumer =================
        const int wn = wid;
        float acc[4][4][4];
#pragma unroll
        for (int mi = 0; mi < 4; ++mi)
#pragma unroll
            for (int ni = 0; ni < 4; ++ni)
#pragma unroll
                for (int q = 0; q < 4; ++q) acc[mi][ni][q] = 0.0f;

        auto issueB = [&](int ci, int stage) {
            int seg = ci >> 2, k0 = (ci & 3) << 5;
            const uint32_t* wsrc = wt + ((size_t)seg << 14) + k0;
            uint32_t bB = sb + (stage ? OFF_B1 : OFF_B0);
#pragma unroll
            for (int j = 0; j < 8; ++j) {
                int i = tid + (j << 7);        // 0..1023
                int c = i >> 3, kv = i & 7;
                cp16(bB + c * (BSTR * 4) + (kv << 4), wsrc + (c << 7) + (kv << 2), true);
            }
        };
        issueB(0, 0); CP_COMMIT();
        issueB(1, 1); CP_COMMIT();

        const uint32_t laneA = (uint32_t)((lid & 15) * (ASTR * 4) + ((lid >> 4) << 4));
        const uint32_t laneB = (uint32_t)(((wn << 5) + ((lid >> 4) << 3) + (lid & 7)) * (BSTR * 4)
                                          + (((lid >> 3) & 1) << 4));

        for (int ci = 0; ci < 44; ++ci) {
            int seg = ci >> 2, stage = ci & 1, buf = seg & 1;
            if ((ci & 3) == 0) BAR_SYNC(buf ? 4 : 1, 256);   // A[seg] ready
            CP_WAIT(1);
            BAR_SYNC(2, 128);
            const uint32_t aA = sb + (buf ? OFF_A1 : OFF_A0) + laneA + ((uint32_t)(ci & 3) << 7);
            const uint32_t bA = sb + (stage ? OFF_B1 : OFF_B0) + laneB;
#pragma unroll
            for (int ks = 0; ks < 4; ++ks) {
                const uint32_t ko = (uint32_t)(ks << 5);
                uint32_t b01[4], b23[4];
                LDSM_X4(b01[0], b01[1], b01[2], b01[3], bA + ko);
                LDSM_X4(b23[0], b23[1], b23[2], b23[3], bA + 16u * BSTR * 4 + ko);
#pragma unroll
                for (int mi = 0; mi < 4; ++mi) {
                    uint32_t a[4];
                    LDSM_X4(a[0], a[1], a[2], a[3], aA + (uint32_t)mi * (16 * ASTR * 4) + ko);
                    mma_tf32(acc[mi][0], a[0], a[1], a[2], a[3], b01[0], b01[1]);
                    mma_tf32(acc[mi][1], a[0], a[1], a[2], a[3], b01[2], b01[3]);
                    mma_tf32(acc[mi][2], a[0], a[1], a[2], a[3], b23[0], b23[1]);
                    mma_tf32(acc[mi][3], a[0], a[1], a[2], a[3], b23[2], b23[3]);
                }
            }
            BAR_SYNC(2, 128);
            if (ci + 2 < 44) issueB(ci + 2, stage);
            CP_COMMIT();
            if ((ci & 3) == 3) BAR_ARRIVE(buf ? 5 : 3, 256);  // A[seg] free
        }

        // epilogue: bias + store
#pragma unroll
        for (int mi = 0; mi < 4; ++mi) {
#pragma unroll
            for (int half = 0; half < 2; ++half) {
                int row = (mi << 4) + (half << 3) + (lid >> 2);
                int g = row0 + row;
                if (g >= N_TGT) continue;
                int t = sTyp[row];
#pragma unroll
                for (int ni = 0; ni < 4; ++ni) {
                    int col = (wn << 5) + (ni << 3) + ((lid & 3) << 1);
                    float2 o;
                    o.x = acc[mi][ni][half * 2 + 0] + rootb[(t << 7) + col];
                    o.y = acc[mi][ni][half * 2 + 1] + rootb[(t << 7) + col + 1];
                    *(float2*)(out + ((size_t)g << 7) + col) = o;
                }
            }
        }
    } else {
        // ================= producer =================
        const int pw = wid - 4;
        for (int seg = 0; seg < NSEG; ++seg) {
            int buf = seg & 1;
            if (seg >= 2) BAR_SYNC(buf ? 5 : 3, 256);
            uint32_t aB = sb + (buf ? OFF_A1 : OFF_A0);
            if (seg < NREL) {
                // gather-aggregate: 16 rows/warp, lane covers channels lid*4..+3.
                // 4-way edge unroll -> 4 concurrent LDGs (MLP).
                for (int rr = 0; rr < 16; ++rr) {
                    int row = (pw << 4) + rr;
                    int g = row0 + row;
                    float4 a0 = make_float4(0.f, 0.f, 0.f, 0.f);
                    float4 a1 = a0, a2 = a0, a3 = a0;
                    if (g < N_TGT) {
                        uint32_t beg = sOfs[row * NREL + seg];
                        uint32_t end = sOfs[row * NREL + seg + 1];
                        uint32_t e = beg;
                        if (useS) {
                            for (; e + 4 <= end; e += 4) {
                                uint32_t s0 = sEl[e - e0],     s1 = sEl[e + 1 - e0];
                                uint32_t s2 = sEl[e + 2 - e0], s3 = sEl[e + 3 - e0];
                                float4 v0 = ((const float4*)(xs + ((size_t)s0 << 7)))[lid];
                                float4 v1 = ((const float4*)(xs + ((size_t)s1 << 7)))[lid];
                                float4 v2 = ((const float4*)(xs + ((size_t)s2 << 7)))[lid];
                                float4 v3 = ((const float4*)(xs + ((size_t)s3 << 7)))[lid];
                                a0.x += v0.x; a0.y += v0.y; a0.z += v0.z; a0.w += v0.w;
                                a1.x += v1.x; a1.y += v1.y; a1.z += v1.z; a1.w += v1.w;
                                a2.x += v2.x; a2.y += v2.y; a2.z += v2.z; a2.w += v2.w;
                                a3.x += v3.x; a3.y += v3.y; a3.z += v3.z; a3.w += v3.w;
                            }
                            for (; e < end; ++e) {
                                uint32_t s = sEl[e - e0];
                                float4 v = ((const float4*)(xs + ((size_t)s << 7)))[lid];
                                a0.x += v.x; a0.y += v.y; a0.z += v.z; a0.w += v.w;
                            }
                        } else {
                            for (; e + 4 <= end; e += 4) {
                                uint32_t s0 = __ldg(elist + e),     s1 = __ldg(elist + e + 1);
                                uint32_t s2 = __ldg(elist + e + 2), s3 = __ldg(elist + e + 3);
                                float4 v0 = ((const float4*)(xs + ((size_t)s0 << 7)))[lid];
                                float4 v1 = ((const float4*)(xs + ((size_t)s1 << 7)))[lid];
                                float4 v2 = ((const float4*)(xs + ((size_t)s2 << 7)))[lid];
                                float4 v3 = ((const float4*)(xs + ((size_t)s3 << 7)))[lid];
                                a0.x += v0.x; a0.y += v0.y; a0.z += v0.z; a0.w += v0.w;
                                a1.x += v1.x; a1.y += v1.y; a1.z += v1.z; a1.w += v1.w;
                                a2.x += v2.x; a2.y += v2.y; a2.z += v2.z; a2.w += v2.w;
                                a3.x += v3.x; a3.y += v3.y; a3.z += v3.z; a3.w += v3.w;
                            }
                            for (; e < end; ++e) {
                                uint32_t s = __ldg(elist + e);
                                float4 v = ((const float4*)(xs + ((size_t)s << 7)))[lid];
                                a0.x += v.x; a0.y += v.y; a0.z += v.z; a0.w += v.w;
                            }
                        }
                        float inv = 1.0f / fmaxf((float)(int)(end - beg), 1.0f);
                        a0.x = (a0.x + a1.x + a2.x + a3.x) * inv;
                        a0.y = (a0.y + a1.y + a2.y + a3.y) * inv;
                        a0.z = (a0.z + a1.z + a2.z + a3.z) * inv;
                        a0.w = (a0.w + a1.w + a2.w + a3.w) * inv;
                    }
                    asm volatile("st.shared.v4.b32 [%0], {%1,%2,%3,%4};"
                        :: "r"(aB + row * (ASTR * 4) + (lid << 4)),
                           "f"(a0.x), "f"(a0.y), "f"(a0.z), "f"(a0.w) : "memory");
                }
            } else {
                // root segment: masked copy of x_target via cp.async (zfill)
                int ty = seg - NREL;
#pragma unroll
                for (int j = 0; j < 16; ++j) {
                    int i = (tid - 128) + (j << 7);   // 0..2047
                    int row = i >> 5, kv = i & 31;    // row 0..63, kv 0..31 (float4s)
                    int g = row0 + row;
                    bool ok = (g < N_TGT) && (sTyp[row] == ty);
                    cp16(aB + row * (ASTR * 4) + (kv << 4),
                         xt + ((size_t)(ok ? g : 0) << 7) + (kv << 2), ok);
                }
                CP_COMMIT(); CP_WAIT(0);
            }
            BAR_ARRIVE(buf ? 4 : 1, 256);     // A[seg] ready
        }
    }
}

extern "C" void kernel_launch(void* const* d_in, const int* in_sizes, int n_in,
                              void* d_out, int out_size)
{
    const float* x_src  = (const float*)d_in[0];
    const float* x_tgt  = (const float*)d_in[1];
    const float* rel_w  = (const float*)d_in[2];
    const float* root_w = (const float*)d_in[3];
    const float* root_b = (const float*)d_in[4];
    const int*   e_src  = (const int*)d_in[5];
    const int*   e_dst  = (const int*)d_in[6];
    const int*   e_typ  = (const int*)d_in[7];
    const int*   n_typ  = (const int*)d_in[8];
    float* out = (float*)d_out;

    void *cntp, *ofsp, *partp, *elp, *wtp;
    cudaGetSymbolAddress(&cntp,  g_bincnt);
    cudaGetSymbolAddress(&ofsp,  g_binofs);
    cudaGetSymbolAddress(&partp, g_part);
    cudaGetSymbolAddress(&elp,   g_elist);
    cudaGetSymbolAddress(&wtp,   g_wtf32);

    cudaMemsetAsync(cntp, 0, NBINS * sizeof(uint32_t));
    hist_kernel<<<(N_EDGES + 255) / 256, 256>>>(e_dst, e_typ, (uint32_t*)cntp);
    scanA_kernel<<<NPART, 1024>>>((const uint32_t*)cntp, (uint32_t*)partp);
    scanC2_kernel<<<NPART, 1024>>>((const uint32_t*)cntp,
                                   (const uint32_t*)partp, (uint32_t*)ofsp);
    fill_kernel<<<(N_EDGES + 255) / 256, 256>>>(e_src, e_dst, e_typ,
                                                (const uint32_t*)ofsp,
                                                (uint32_t*)cntp, (uint32_t*)elp);
    prep_weights<<<(NSEG * CH * CH / 4 + 255) / 256, 256>>>(rel_w, root_w, (uint32_t*)wtp);

    cudaFuncSetAttribute(fused_kernel,
                         cudaFuncAttributeMaxDynamicSharedMemorySize, SMEM_TOTAL);
    fused_kernel<<<(N_TGT + TILE_M - 1) / TILE_M, 256, SMEM_TOTAL>>>(
        x_src, x_tgt, (const uint32_t*)wtp, root_b, n_typ,
        (const uint32_t*)ofsp, (const uint32_t*)elp, out);
}

// round 13
// speedup vs baseline: 1.0663x; 1.0663x over previous
#include <cuda_runtime.h>
#include <cstdint>

#define N_SRC   100000
#define N_TGT   50000
#define N_EDGES 600000
#define CH      128
#define NREL    7
#define NTYP    4
#define NSEG    11
#define NBINS   (N_TGT * NREL)          // 350000
#define NPART   342                     // ceil(NBINS/1024)

// Fused kernel tiling
#define TILE_M  64
#define ASTR    132                     // A row stride (words): 128 + 4 pad
#define A_BYTES (TILE_M * ASTR * 4)     // 33792 per buffer
#define BSTR    36                      // B row stride (words)
#define B_BYTES (128 * BSTR * 4)        // 18432 per stage
#define ELIST_CAP 1536

#define OFF_A0  0
#define OFF_A1  A_BYTES
#define OFF_B0  (2 * A_BYTES)
#define OFF_B1  (2 * A_BYTES + B_BYTES)
#define OFF_OFS (2 * A_BYTES + 2 * B_BYTES)
#define OFF_TYP (OFF_OFS + 452 * 4)
#define OFF_EL  (OFF_TYP + 64 * 4)
#define SMEM_TOTAL (OFF_EL + ELIST_CAP * 4)   // 112656 bytes -> 2 CTAs/SM

// Scratch (allocation-free rule: __device__ globals).
// g_bincnt: zero-initialized at module load; fill_kernel's atomicSub drains it
// back to zero every invocation -> no memset needed (self-restoring invariant).
__device__ uint32_t g_bincnt[NBINS];
__device__ uint32_t g_binofs[NBINS + 1];
__device__ uint32_t g_part[NPART];
__device__ uint32_t g_elist[N_EDGES];
__device__ uint32_t g_wtf32[NSEG * CH * CH];

// ---------------- helpers ----------------
__device__ __forceinline__ uint32_t to_tf32(float x) {
    uint32_t r;
    asm("cvt.rna.tf32.f32 %0, %1;" : "=r"(r) : "f"(x));
    return r;
}
__device__ __forceinline__ uint32_t smem_u32(const void* p) {
    uint32_t a;
    asm("{ .reg .u64 t; cvta.to.shared.u64 t, %1; cvt.u32.u64 %0, t; }" : "=r"(a) : "l"(p));
    return a;
}
__device__ __forceinline__ void cp16(uint32_t dst, const void* src, bool pred) {
    asm volatile("cp.async.ca.shared.global [%0], [%1], 16, %2;"
                 :: "r"(dst), "l"(src), "r"(pred ? 16 : 0) : "memory");
}
#define CP_COMMIT() asm volatile("cp.async.commit_group;" ::: "memory")
#define CP_WAIT(n)  asm volatile("cp.async.wait_group %0;" :: "n"(n) : "memory")
#define BAR_SYNC(id, cnt)   asm volatile("bar.sync %0, %1;"   :: "r"(id), "r"(cnt) : "memory")
#define BAR_ARRIVE(id, cnt) asm volatile("bar.arrive %0, %1;" :: "r"(id), "r"(cnt) : "memory")
#define LDSM_X4(r0, r1, r2, r3, addr) \
    asm volatile("ldmatrix.sync.aligned.m8n8.x4.shared.b16 {%0,%1,%2,%3}, [%4];" \
        : "=r"(r0), "=r"(r1), "=r"(r2), "=r"(r3) : "r"(addr))

__device__ __forceinline__ void mma_tf32(float* c,
    uint32_t a0, uint32_t a1, uint32_t a2, uint32_t a3,
    uint32_t b0, uint32_t b1)
{
    asm volatile(
        "mma.sync.aligned.m16n8k8.row.col.f32.tf32.tf32.f32 "
        "{%0,%1,%2,%3}, {%4,%5,%6,%7}, {%8,%9}, {%0,%1,%2,%3};"
        : "+f"(c[0]), "+f"(c[1]), "+f"(c[2]), "+f"(c[3])
        : "r"(a0), "r"(a1), "r"(a2), "r"(a3), "r"(b0), "r"(b1));
}

// ---------------- CSR build ----------------
__global__ __launch_bounds__(256) void hist_kernel(
    const int* __restrict__ edst, const int* __restrict__ etyp,
    uint32_t* __restrict__ cnt)
{
    int e = blockIdx.x * 256 + threadIdx.x;
    if (e >= N_EDGES) return;
    atomicAdd(&cnt[__ldg(edst + e) * NREL + __ldg(etyp + e)], 1u);
}

__global__ __launch_bounds__(1024) void scanA_kernel(
    const uint32_t* __restrict__ cnt, uint32_t* __restrict__ part)
{
    __shared__ uint32_t s[1024];
    int t = threadIdx.x;
    int i = blockIdx.x * 1024 + t;
    s[t] = (i < NBINS) ? cnt[i] : 0u;
    __syncthreads();
    for (int off = 512; off; off >>= 1) {
        if (t < off) s[t] += s[t + off];
        __syncthreads();
    }
    if (t == 0) part[blockIdx.x] = s[0];
}

// scanC2: per-block exclusive prefix over part[] computed locally (reduction),
// then block-local inclusive scan of cnt -> global exclusive bin offsets.
__global__ __launch_bounds__(1024) void scanC2_kernel(
    const uint32_t* __restrict__ cnt, const uint32_t* __restrict__ part,
    uint32_t* __restrict__ ofs)
{
    __shared__ uint32_t s[1024];
    __shared__ uint32_t sp[1024];
    __shared__ uint32_t blockPrefix;
    int t = threadIdx.x;
    int b = blockIdx.x;
    uint32_t p = 0;
    for (int i = t; i < b; i += 1024) p += part[i];
    sp[t] = p;
    __syncthreads();
    for (int off = 512; off; off >>= 1) {
        if (t < off) sp[t] += sp[t + off];
        __syncthreads();
    }
    if (t == 0) blockPrefix = sp[0];
    int i = b * 1024 + t;
    uint32_t v = (i < NBINS) ? cnt[i] : 0u;
    s[t] = v;
    __syncthreads();
    for (int off = 1; off < 1024; off <<= 1) {
        uint32_t x = (t >= off) ? s[t - off] : 0u;
        __syncthreads();
        s[t] += x;
        __syncthreads();
    }
    if (i < NBINS) ofs[i] = s[t] - v + blockPrefix;
    if (b == 0 && t == 0) ofs[NBINS] = N_EDGES;
}

// fill: consumes bincnt as the cursor (atomicSub) -> drains cnt back to zero,
// restoring the pre-hist state for the next invocation.
__global__ __launch_bounds__(256) void fill_kernel(
    const int* __restrict__ esrc, const int* __restrict__ edst,
    const int* __restrict__ etyp,
    const uint32_t* __restrict__ ofs, uint32_t* __restrict__ cnt,
    uint32_t* __restrict__ elist)
{
    int e = blockIdx.x * 256 + threadIdx.x;
    if (e >= N_EDGES) return;
    int bin = __ldg(edst + e) * NREL + __ldg(etyp + e);
    uint32_t idx = atomicSub(&cnt[bin], 1u) - 1u;
    elist[ofs[bin] + idx] = (uint32_t)__ldg(esrc + e);
}

// ---------------- weight pre-convert (B in rna tf32: accuracy margin) -----
__global__ __launch_bounds__(256) void prep_weights(
    const float* __restrict__ relw, const float* __restrict__ rootw,
    uint32_t* __restrict__ wt)
{
    int i = blockIdx.x * 256 + threadIdx.x;
    const int NREL4 = NREL * CH * CH / 4;
    const int TOT4  = NSEG * CH * CH / 4;
    if (i >= TOT4) return;
    float4 v = (i < NREL4) ? ((const float4*)relw)[i]
                           : ((const float4*)rootw)[i - NREL4];
    uint4 w;
    w.x = to_tf32(v.x); w.y = to_tf32(v.y);
    w.z = to_tf32(v.z); w.w = to_tf32(v.w);
    ((uint4*)wt)[i] = w;
}

// ---------------- fused warp-specialized aggregate+GEMM ----------------
// Warps 0-3: consumers (MMA, 64x32 warp tile each).  Warps 4-7: producers
// (gather-aggregate relation A tiles; masked-copy root A tiles).
// Named barriers: 1/4 = A buf even/odd ready; 3/5 = A buf even/odd free;
// 2 = consumer-local B staging.
__global__ __launch_bounds__(256, 2) void fused_kernel(
    const float* __restrict__ xs, const float* __restrict__ xt,
    const uint32_t* __restrict__ wt, const float* __restrict__ rootb,
    const int* __restrict__ ttype,
    const uint32_t* __restrict__ binofs, const uint32_t* __restrict__ elist,
    float* __restrict__ out)
{
    extern __shared__ char smc[];
    const uint32_t sb = smem_u32(smc);
    uint32_t* sOfs = (uint32_t*)(smc + OFF_OFS);
    int*      sTyp = (int*)(smc + OFF_TYP);
    uint32_t* sEl  = (uint32_t*)(smc + OFF_EL);

    const int tid = threadIdx.x;
    const int wid = tid >> 5;
    const int lid = tid & 31;
    const int row0 = blockIdx.x * TILE_M;

    for (int i = tid; i < 449; i += 256) {
        int idx = row0 * NREL + i;
        if (idx > NBINS) idx = NBINS;
        sOfs[i] = binofs[idx];
    }
    if (tid < TILE_M) {
        int g = row0 + tid;
        sTyp[tid] = (g < N_TGT) ? ttype[g] : -1;
    }
    __syncthreads();
    const uint32_t e0 = sOfs[0];
    const int nEdge = (int)(sOfs[448] - e0);
    const bool useS = (nEdge <= ELIST_CAP);
    if (useS)
        for (int i = tid; i < nEdge; i += 256) sEl[i] = elist[e0 + i];
    __syncthreads();

    if (wid < 4) {
        // ================= consumer =================
        const int wn = wid;
        float acc[4][4][4];
#pragma unroll
        for (int mi = 0; mi < 4; ++mi)
#pragma unroll
            for (int ni = 0; ni < 4; ++ni)
#pragma unroll
                for (int q = 0; q < 4; ++q) acc[mi][ni][q] = 0.0f;

        auto issueB = [&](int ci, int stage) {
            int seg = ci >> 2, k0 = (ci & 3) << 5;
            const uint32_t* wsrc = wt + ((size_t)seg << 14) + k0;
            uint32_t bB = sb + (stage ? OFF_B1 : OFF_B0);
#pragma unroll
            for (int j = 0; j < 8; ++j) {
                int i = tid + (j << 7);        // 0..1023
                int c = i >> 3, kv = i & 7;
                cp16(bB + c * (BSTR * 4) + (kv << 4), wsrc + (c << 7) + (kv << 2), true);
            }
        };
        issueB(0, 0); CP_COMMIT();
        issueB(1, 1); CP_COMMIT();

        const uint32_t laneA = (uint32_t)((lid & 15) * (ASTR * 4) + ((lid >> 4) << 4));
        const uint32_t laneB = (uint32_t)(((wn << 5) + ((lid >> 4) << 3) + (lid & 7)) * (BSTR * 4)
                                          + (((lid >> 3) & 1) << 4));

        for (int ci = 0; ci < 44; ++ci) {
            int seg = ci >> 2, stage = ci & 1, buf = seg & 1;
            if ((ci & 3) == 0) BAR_SYNC(buf ? 4 : 1, 256);   // A[seg] ready
            CP_WAIT(1);
            BAR_SYNC(2, 128);
            const uint32_t aA = sb + (buf ? OFF_A1 : OFF_A0) + laneA + ((uint32_t)(ci & 3) << 7);
            const uint32_t bA = sb + (stage ? OFF_B1 : OFF_B0) + laneB;
#pragma unroll
            for (int ks = 0; ks < 4; ++ks) {
                const uint32_t ko = (uint32_t)(ks << 5);
                uint32_t b01[4], b23[4];
                LDSM_X4(b01[0], b01[1], b01[2], b01[3], bA + ko);
                LDSM_X4(b23[0], b23[1], b23[2], b23[3], bA + 16u * BSTR * 4 + ko);
#pragma unroll
                for (int mi = 0; mi < 4; ++mi) {
                    uint32_t a[4];
                    LDSM_X4(a[0], a[1], a[2], a[3], aA + (uint32_t)mi * (16 * ASTR * 4) + ko);
                    mma_tf32(acc[mi][0], a[0], a[1], a[2], a[3], b01[0], b01[1]);
                    mma_tf32(acc[mi][1], a[0], a[1], a[2], a[3], b01[2], b01[3]);
                    mma_tf32(acc[mi][2], a[0], a[1], a[2], a[3], b23[0], b23[1]);
                    mma_tf32(acc[mi][3], a[0], a[1], a[2], a[3], b23[2], b23[3]);
                }
            }
            BAR_SYNC(2, 128);
            if (ci + 2 < 44) issueB(ci + 2, stage);
            CP_COMMIT();
            if ((ci & 3) == 3) BAR_ARRIVE(buf ? 5 : 3, 256);  // A[seg] free
        }

        // epilogue: bias + store
#pragma unroll
        for (int mi = 0; mi < 4; ++mi) {
#pragma unroll
            for (int half = 0; half < 2; ++half) {
                int row = (mi << 4) + (half << 3) + (lid >> 2);
                int g = row0 + row;
                if (g >= N_TGT) continue;
                int t = sTyp[row];
#pragma unroll
                for (int ni = 0; ni < 4; ++ni) {
                    int col = (wn << 5) + (ni << 3) + ((lid & 3) << 1);
                    float2 o;
                    o.x = acc[mi][ni][half * 2 + 0] + rootb[(t << 7) + col];
                    o.y = acc[mi][ni][half * 2 + 1] + rootb[(t << 7) + col + 1];
                    *(float2*)(out + ((size_t)g << 7) + col) = o;
                }
            }
        }
    } else {
        // ================= producer =================
        const int pw = wid - 4;
        for (int seg = 0; seg < NSEG; ++seg) {
            int buf = seg & 1;
            if (seg >= 2) BAR_SYNC(buf ? 5 : 3, 256);
            uint32_t aB = sb + (buf ? OFF_A1 : OFF_A0);
            if (seg < NREL) {
                // gather-aggregate 16 rows per warp; lane covers channels lid*4..+3
#pragma unroll 2
                for (int rr = 0; rr < 16; ++rr) {
                    int row = (pw << 4) + rr;
                    int g = row0 + row;
                    float4 a = make_float4(0.f, 0.f, 0.f, 0.f);
                    if (g < N_TGT) {
                        uint32_t beg = sOfs[row * NREL + seg];
                        uint32_t end = sOfs[row * NREL + seg + 1];
                        if (useS) {
                            for (uint32_t e = beg; e < end; ++e) {
                                uint32_t s = sEl[e - e0];
                                float4 v = ((const float4*)(xs + ((size_t)s << 7)))[lid];
                                a.x += v.x; a.y += v.y; a.z += v.z; a.w += v.w;
                            }
                        } else {
                            for (uint32_t e = beg; e < end; ++e) {
                                uint32_t s = __ldg(elist + e);
                                float4 v = ((const float4*)(xs + ((size_t)s << 7)))[lid];
                                a.x += v.x; a.y += v.y; a.z += v.z; a.w += v.w;
                            }
                        }
                        float inv = 1.0f / fmaxf((float)(int)(end - beg), 1.0f);
                        a.x *= inv; a.y *= inv; a.z *= inv; a.w *= inv;
                    }
                    asm volatile("st.shared.v4.b32 [%0], {%1,%2,%3,%4};"
                        :: "r"(aB + row * (ASTR * 4) + (lid << 4)),
                           "f"(a.x), "f"(a.y), "f"(a.z), "f"(a.w) : "memory");
                }
            } else {
                // root segment: masked copy of x_target via cp.async (zfill)
                int ty = seg - NREL;
#pragma unroll
                for (int j = 0; j < 16; ++j) {
                    int i = (tid - 128) + (j << 7);   // 0..2047
                    int row = i >> 5, kv = i & 31;    // row 0..63, kv 0..31 (float4s)
                    int g = row0 + row;
                    bool ok = (g < N_TGT) && (sTyp[row] == ty);
                    cp16(aB + row * (ASTR * 4) + (kv << 4),
                         xt + ((size_t)(ok ? g : 0) << 7) + (kv << 2), ok);
                }
                CP_COMMIT(); CP_WAIT(0);
            }
            BAR_ARRIVE(buf ? 4 : 1, 256);     // A[seg] ready
        }
    }
}

extern "C" void kernel_launch(void* const* d_in, const int* in_sizes, int n_in,
                              void* d_out, int out_size)
{
    const float* x_src  = (const float*)d_in[0];
    const float* x_tgt  = (const float*)d_in[1];
    const float* rel_w  = (const float*)d_in[2];
    const float* root_w = (const float*)d_in[3];
    const float* root_b = (const float*)d_in[4];
    const int*   e_src  = (const int*)d_in[5];
    const int*   e_dst  = (const int*)d_in[6];
    const int*   e_typ  = (const int*)d_in[7];
    const int*   n_typ  = (const int*)d_in[8];
    float* out = (float*)d_out;

    void *cntp, *ofsp, *partp, *elp, *wtp;
    cudaGetSymbolAddress(&cntp,  g_bincnt);
    cudaGetSymbolAddress(&ofsp,  g_binofs);
    cudaGetSymbolAddress(&partp, g_part);
    cudaGetSymbolAddress(&elp,   g_elist);
    cudaGetSymbolAddress(&wtp,   g_wtf32);

    // No memset: g_bincnt starts zeroed (module load) and fill_kernel's
    // atomicSub drains it back to zero every invocation.
    hist_kernel<<<(N_EDGES + 255) / 256, 256>>>(e_dst, e_typ, (uint32_t*)cntp);
    scanA_kernel<<<NPART, 1024>>>((const uint32_t*)cntp, (uint32_t*)partp);
    scanC2_kernel<<<NPART, 1024>>>((const uint32_t*)cntp,
                                   (const uint32_t*)partp, (uint32_t*)ofsp);
    fill_kernel<<<(N_EDGES + 255) / 256, 256>>>(e_src, e_dst, e_typ,
                                                (const uint32_t*)ofsp,
                                                (uint32_t*)cntp, (uint32_t*)elp);
    prep_weights<<<(NSEG * CH * CH / 4 + 255) / 256, 256>>>(rel_w, root_w, (uint32_t*)wtp);

    cudaFuncSetAttribute(fused_kernel,
                         cudaFuncAttributeMaxDynamicSharedMemorySize, SMEM_TOTAL);
    fused_kernel<<<(N_TGT + TILE_M - 1) / TILE_M, 256, SMEM_TOTAL>>>(
        x_src, x_tgt, (const uint32_t*)wtp, root_b, n_typ,
        (const uint32_t*)ofsp, (const uint32_t*)elp, out);
}

// round 14
// speedup vs baseline: 1.0942x; 1.0262x over previous
#include <cuda_runtime.h>
#include <cstdint>

#define N_SRC   100000
#define N_TGT   50000
#define N_EDGES 600000
#define CH      128
#define NREL    7
#define NTYP    4
#define NSEG    11
#define NBINS   (N_TGT * NREL)          // 350000
#define NPART   342                     // ceil(NBINS/1024)

// Fused kernel tiling
#define TILE_M  64
#define ASTR    132                     // A row stride (words): 128 + 4 pad
#define A_BYTES (TILE_M * ASTR * 4)     // 33792 per buffer
#define BSTR    36                      // B row stride (words)
#define B_BYTES (128 * BSTR * 4)        // 18432 per stage
#define ELIST_CAP 1536

#define OFF_A0  0
#define OFF_A1  A_BYTES
#define OFF_B0  (2 * A_BYTES)
#define OFF_B1  (2 * A_BYTES + B_BYTES)
#define OFF_OFS (2 * A_BYTES + 2 * B_BYTES)
#define OFF_TYP (OFF_OFS + 452 * 4)
#define OFF_EL  (OFF_TYP + 64 * 4)
#define SMEM_TOTAL (OFF_EL + ELIST_CAP * 4)   // 112656 bytes -> 2 CTAs/SM

// Scratch (allocation-free rule: __device__ globals).
// g_bincnt: zeroed at module load; fill_kernel's atomicSub drains it back to
// zero every invocation -> no memset needed (self-restoring invariant).
__device__ uint32_t g_bincnt[NBINS];
__device__ uint32_t g_binofs[NBINS + 1];
__device__ uint32_t g_part[NPART];
__device__ uint32_t g_elist[N_EDGES];
__device__ uint32_t g_wtf32[NSEG * CH * CH];

// ---------------- helpers ----------------
__device__ __forceinline__ uint32_t to_tf32(float x) {
    uint32_t r;
    asm("cvt.rna.tf32.f32 %0, %1;" : "=r"(r) : "f"(x));
    return r;
}
__device__ __forceinline__ uint32_t smem_u32(const void* p) {
    uint32_t a;
    asm("{ .reg .u64 t; cvta.to.shared.u64 t, %1; cvt.u32.u64 %0, t; }" : "=r"(a) : "l"(p));
    return a;
}
__device__ __forceinline__ void cp16(uint32_t dst, const void* src, bool pred) {
    asm volatile("cp.async.ca.shared.global [%0], [%1], 16, %2;"
                 :: "r"(dst), "l"(src), "r"(pred ? 16 : 0) : "memory");
}
#define CP_COMMIT() asm volatile("cp.async.commit_group;" ::: "memory")
#define CP_WAIT(n)  asm volatile("cp.async.wait_group %0;" :: "n"(n) : "memory")
#define LDSM_X4(r0, r1, r2, r3, addr) \
    asm volatile("ldmatrix.sync.aligned.m8n8.x4.shared.b16 {%0,%1,%2,%3}, [%4];" \
        : "=r"(r0), "=r"(r1), "=r"(r2), "=r"(r3) : "r"(addr))

__device__ __forceinline__ void mma_tf32(float* c,
    uint32_t a0, uint32_t a1, uint32_t a2, uint32_t a3,
    uint32_t b0, uint32_t b1)
{
    asm volatile(
        "mma.sync.aligned.m16n8k8.row.col.f32.tf32.tf32.f32 "
        "{%0,%1,%2,%3}, {%4,%5,%6,%7}, {%8,%9}, {%0,%1,%2,%3};"
        : "+f"(c[0]), "+f"(c[1]), "+f"(c[2]), "+f"(c[3])
        : "r"(a0), "r"(a1), "r"(a2), "r"(a3), "r"(b0), "r"(b1));
}

// ---------------- CSR build ----------------
__global__ __launch_bounds__(256) void hist_kernel(
    const int* __restrict__ edst, const int* __restrict__ etyp,
    uint32_t* __restrict__ cnt)
{
    int e = blockIdx.x * 256 + threadIdx.x;
    if (e >= N_EDGES) return;
    atomicAdd(&cnt[__ldg(edst + e) * NREL + __ldg(etyp + e)], 1u);
}

__global__ __launch_bounds__(1024) void scanA_kernel(
    const uint32_t* __restrict__ cnt, uint32_t* __restrict__ part)
{
    __shared__ uint32_t s[1024];
    int t = threadIdx.x;
    int i = blockIdx.x * 1024 + t;
    s[t] = (i < NBINS) ? cnt[i] : 0u;
    __syncthreads();
    for (int off = 512; off; off >>= 1) {
        if (t < off) s[t] += s[t + off];
        __syncthreads();
    }
    if (t == 0) part[blockIdx.x] = s[0];
}

__global__ __launch_bounds__(1024) void scanC2_kernel(
    const uint32_t* __restrict__ cnt, const uint32_t* __restrict__ part,
    uint32_t* __restrict__ ofs)
{
    __shared__ uint32_t s[1024];
    __shared__ uint32_t sp[1024];
    __shared__ uint32_t blockPrefix;
    int t = threadIdx.x;
    int b = blockIdx.x;
    uint32_t p = 0;
    for (int i = t; i < b; i += 1024) p += part[i];
    sp[t] = p;
    __syncthreads();
    for (int off = 512; off; off >>= 1) {
        if (t < off) sp[t] += sp[t + off];
        __syncthreads();
    }
    if (t == 0) blockPrefix = sp[0];
    int i = b * 1024 + t;
    uint32_t v = (i < NBINS) ? cnt[i] : 0u;
    s[t] = v;
    __syncthreads();
    for (int off = 1; off < 1024; off <<= 1) {
        uint32_t x = (t >= off) ? s[t - off] : 0u;
        __syncthreads();
        s[t] += x;
        __syncthreads();
    }
    if (i < NBINS) ofs[i] = s[t] - v + blockPrefix;
    if (b == 0 && t == 0) ofs[NBINS] = N_EDGES;
}

__global__ __launch_bounds__(256) void fill_kernel(
    const int* __restrict__ esrc, const int* __restrict__ edst,
    const int* __restrict__ etyp,
    const uint32_t* __restrict__ ofs, uint32_t* __restrict__ cnt,
    uint32_t* __restrict__ elist)
{
    int e = blockIdx.x * 256 + threadIdx.x;
    if (e >= N_EDGES) return;
    int bin = __ldg(edst + e) * NREL + __ldg(etyp + e);
    uint32_t idx = atomicSub(&cnt[bin], 1u) - 1u;
    elist[ofs[bin] + idx] = (uint32_t)__ldg(esrc + e);
}

// ---------------- weight pre-convert ----------------
__global__ __launch_bounds__(256) void prep_weights(
    const float* __restrict__ relw, const float* __restrict__ rootw,
    uint32_t* __restrict__ wt)
{
    int i = blockIdx.x * 256 + threadIdx.x;
    const int NREL4 = NREL * CH * CH / 4;
    const int TOT4  = NSEG * CH * CH / 4;
    if (i >= TOT4) return;
    float4 v = (i < NREL4) ? ((const float4*)relw)[i]
                           : ((const float4*)rootw)[i - NREL4];
    uint4 w;
    w.x = to_tf32(v.x); w.y = to_tf32(v.y);
    w.z = to_tf32(v.z); w.w = to_tf32(v.w);
    ((uint4*)wt)[i] = w;
}

// ---------------- fused bulk-synchronous aggregate+GEMM ----------------
// All 8 warps alternate phases per segment: gather A[seg+1] into alt buffer,
// then run the R7-proven LDSM/MMA mainloop (32x32 warp tiles) on A[seg].
// B: 2-stage cp.async pipeline from pre-converted tf32 weights.
__global__ __launch_bounds__(256, 2) void fused_kernel(
    const float* __restrict__ xs, const float* __restrict__ xt,
    const uint32_t* __restrict__ wt, const float* __restrict__ rootb,
    const int* __restrict__ ttype,
    const uint32_t* __restrict__ binofs, const uint32_t* __restrict__ elist,
    float* __restrict__ out)
{
    extern __shared__ char smc[];
    const uint32_t sb = smem_u32(smc);
    uint32_t* sOfs = (uint32_t*)(smc + OFF_OFS);
    int*      sTyp = (int*)(smc + OFF_TYP);
    uint32_t* sEl  = (uint32_t*)(smc + OFF_EL);

    const int tid = threadIdx.x;
    const int wid = tid >> 5;
    const int lid = tid & 31;
    const int wm = wid & 1;        // 32-row half
    const int wn = wid >> 1;       // 32-col quarter
    const int row0 = blockIdx.x * TILE_M;

    for (int i = tid; i < 449; i += 256) {
        int idx = row0 * NREL + i;
        if (idx > NBINS) idx = NBINS;
        sOfs[i] = binofs[idx];
    }
    if (tid < TILE_M) {
        int g = row0 + tid;
        sTyp[tid] = (g < N_TGT) ? ttype[g] : -1;
    }
    __syncthreads();
    const uint32_t e0 = sOfs[0];
    const int nEdge = (int)(sOfs[448] - e0);
    const bool useS = (nEdge <= ELIST_CAP);
    if (useS)
        for (int i = tid; i < nEdge; i += 256) sEl[i] = elist[e0 + i];
    __syncthreads();

    // ---- B stage loader: 1024 float4 over 256 threads ----
    auto issueB = [&](int ci) {
        int seg = ci >> 2, k0 = (ci & 3) << 5;
        const uint32_t* wsrc = wt + ((size_t)seg << 14) + k0;
        uint32_t bB = sb + ((ci & 1) ? OFF_B1 : OFF_B0);
#pragma unroll
        for (int j = 0; j < 4; ++j) {
            int i = tid + (j << 8);
            int c = i >> 3, kv = i & 7;
            cp16(bB + c * (BSTR * 4) + (kv << 4), wsrc + (c << 7) + (kv << 2), true);
        }
    };

    // ---- A gather/copy: 8 rows per warp into buffer buf ----
    auto buildA = [&](int seg, int buf) {
        uint32_t aB = sb + (buf ? OFF_A1 : OFF_A0);
        if (seg < NREL) {
#pragma unroll 2
            for (int rr = 0; rr < 8; ++rr) {
                int row = (wid << 3) + rr;
                int g = row0 + row;
                float4 a = make_float4(0.f, 0.f, 0.f, 0.f);
                if (g < N_TGT) {
                    uint32_t beg = sOfs[row * NREL + seg];
                    uint32_t end = sOfs[row * NREL + seg + 1];
                    if (useS) {
                        for (uint32_t e = beg; e < end; ++e) {
                            uint32_t s = sEl[e - e0];
                            float4 v = ((const float4*)(xs + ((size_t)s << 7)))[lid];
                            a.x += v.x; a.y += v.y; a.z += v.z; a.w += v.w;
                        }
                    } else {
                        for (uint32_t e = beg; e < end; ++e) {
                            uint32_t s = __ldg(elist + e);
                            float4 v = ((const float4*)(xs + ((size_t)s << 7)))[lid];
                            a.x += v.x; a.y += v.y; a.z += v.z; a.w += v.w;
                        }
                    }
                    float inv = 1.0f / fmaxf((float)(int)(end - beg), 1.0f);
                    a.x *= inv; a.y *= inv; a.z *= inv; a.w *= inv;
                }
                asm volatile("st.shared.v4.b32 [%0], {%1,%2,%3,%4};"
                    :: "r"(aB + row * (ASTR * 4) + (lid << 4)),
                       "f"(a.x), "f"(a.y), "f"(a.z), "f"(a.w) : "memory");
            }
        } else {
            int ty = seg - NREL;
#pragma unroll 2
            for (int rr = 0; rr < 8; ++rr) {
                int row = (wid << 3) + rr;
                int g = row0 + row;
                bool ok = (g < N_TGT) && (sTyp[row] == ty);
                float4 a = make_float4(0.f, 0.f, 0.f, 0.f);
                if (ok) a = ((const float4*)(xt + ((size_t)g << 7)))[lid];
                asm volatile("st.shared.v4.b32 [%0], {%1,%2,%3,%4};"
                    :: "r"(aB + row * (ASTR * 4) + (lid << 4)),
                       "f"(a.x), "f"(a.y), "f"(a.z), "f"(a.w) : "memory");
            }
        }
    };

    float acc[2][4][4];
#pragma unroll
    for (int mi = 0; mi < 2; ++mi)
#pragma unroll
        for (int ni = 0; ni < 4; ++ni)
#pragma unroll
            for (int q = 0; q < 4; ++q) acc[mi][ni][q] = 0.0f;

    // prologue: B pipeline first (LDGs overlap the seg-0 gather), then A[0]
    issueB(0); CP_COMMIT();
    issueB(1); CP_COMMIT();
    buildA(0, 0);

    // ldmatrix lane addressing (R7-proven)
    const uint32_t laneA = (uint32_t)((((wm << 5) + (lid & 15)) * (ASTR * 4))
                                      + ((lid >> 4) << 4));
    const uint32_t laneB = (uint32_t)((((wn << 5) + ((lid >> 4) << 3) + (lid & 7)) * (BSTR * 4))
                                      + (((lid >> 3) & 1) << 4));
    const uint32_t MI_OFF = 16u * ASTR * 4;
    const uint32_t NI_OFF = 16u * BSTR * 4;

    for (int seg = 0; seg < NSEG; ++seg) {
        int buf = seg & 1;
        if (seg + 1 < NSEG) buildA(seg + 1, buf ^ 1);   // writes other buffer
        const uint32_t aA = sb + (buf ? OFF_A1 : OFF_A0) + laneA;
#pragma unroll
        for (int c = 0; c < 4; ++c) {
            int ci = (seg << 2) + c;
            CP_WAIT(1);                 // B chunk ci landed (this thread)
            __syncthreads();            // ...for all threads; A[seg] visible (c==0)
            const uint32_t aC = aA + ((uint32_t)c << 7);
            const uint32_t bA = sb + ((ci & 1) ? OFF_B1 : OFF_B0) + laneB;
#pragma unroll
            for (int ks = 0; ks < 4; ++ks) {
                const uint32_t ko = (uint32_t)(ks << 5);
                uint32_t a0[4], a1[4], b01[4], b23[4];
                LDSM_X4(a0[0], a0[1], a0[2], a0[3], aC + ko);
                LDSM_X4(a1[0], a1[1], a1[2], a1[3], aC + MI_OFF + ko);
                LDSM_X4(b01[0], b01[1], b01[2], b01[3], bA + ko);
                LDSM_X4(b23[0], b23[1], b23[2], b23[3], bA + NI_OFF + ko);
                mma_tf32(acc[0][0], a0[0], a0[1], a0[2], a0[3], b01[0], b01[1]);
                mma_tf32(acc[0][1], a0[0], a0[1], a0[2], a0[3], b01[2], b01[3]);
                mma_tf32(acc[0][2], a0[0], a0[1], a0[2], a0[3], b23[0], b23[1]);
                mma_tf32(acc[0][3], a0[0], a0[1], a0[2], a0[3], b23[2], b23[3]);
                mma_tf32(acc[1][0], a1[0], a1[1], a1[2], a1[3], b01[0], b01[1]);
                mma_tf32(acc[1][1], a1[0], a1[1], a1[2], a1[3], b01[2], b01[3]);
                mma_tf32(acc[1][2], a1[0], a1[1], a1[2], a1[3], b23[0], b23[1]);
                mma_tf32(acc[1][3], a1[0], a1[1], a1[2], a1[3], b23[2], b23[3]);
            }
            __syncthreads();            // B stage reusable
            if (ci + 2 < 4 * NSEG) issueB(ci + 2);
            CP_COMMIT();                // uniform group accounting
        }
    }

    // ---- epilogue: bias + store ----
#pragma unroll
    for (int mi = 0; mi < 2; ++mi) {
#pragma unroll
        for (int half = 0; half < 2; ++half) {
            int row = (wm << 5) + (mi << 4) + (half << 3) + (lid >> 2);
            int g = row0 + row;
            if (g >= N_TGT) continue;
            int t = sTyp[row];
#pragma unroll
            for (int ni = 0; ni < 4; ++ni) {
                int col = (wn << 5) + (ni << 3) + ((lid & 3) << 1);
                float2 o;
                o.x = acc[mi][ni][half * 2 + 0] + rootb[(t << 7) + col];
                o.y = acc[mi][ni][half * 2 + 1] + rootb[(t << 7) + col + 1];
                *(float2*)(out + ((size_t)g << 7) + col) = o;
            }
        }
    }
}

extern "C" void kernel_launch(void* const* d_in, const int* in_sizes, int n_in,
                              void* d_out, int out_size)
{
    const float* x_src  = (const float*)d_in[0];
    const float* x_tgt  = (const float*)d_in[1];
    const float* rel_w  = (const float*)d_in[2];
    const float* root_w = (const float*)d_in[3];
    const float* root_b = (const float*)d_in[4];
    const int*   e_src  = (const int*)d_in[5];
    const int*   e_dst  = (const int*)d_in[6];
    const int*   e_typ  = (const int*)d_in[7];
    const int*   n_typ  = (const int*)d_in[8];
    float* out = (float*)d_out;

    void *cntp, *ofsp, *partp, *elp, *wtp;
    cudaGetSymbolAddress(&cntp,  g_bincnt);
    cudaGetSymbolAddress(&ofsp,  g_binofs);
    cudaGetSymbolAddress(&partp, g_part);
    cudaGetSymbolAddress(&elp,   g_elist);
    cudaGetSymbolAddress(&wtp,   g_wtf32);

    hist_kernel<<<(N_EDGES + 255) / 256, 256>>>(e_dst, e_typ, (uint32_t*)cntp);
    scanA_kernel<<<NPART, 1024>>>((const uint32_t*)cntp, (uint32_t*)partp);
    scanC2_kernel<<<NPART, 1024>>>((const uint32_t*)cntp,
                                   (const uint32_t*)partp, (uint32_t*)ofsp);
    fill_kernel<<<(N_EDGES + 255) / 256, 256>>>(e_src, e_dst, e_typ,
                                                (const uint32_t*)ofsp,
                                                (uint32_t*)cntp, (uint32_t*)elp);
    prep_weights<<<(NSEG * CH * CH / 4 + 255) / 256, 256>>>(rel_w, root_w, (uint32_t*)wtp);

    cudaFuncSetAttribute(fused_kernel,
                         cudaFuncAttributeMaxDynamicSharedMemorySize, SMEM_TOTAL);
    fused_kernel<<<(N_TGT + TILE_M - 1) / TILE_M, 256, SMEM_TOTAL>>>(
        x_src, x_tgt, (const uint32_t*)wtp, root_b, n_typ,
        (const uint32_t*)ofsp, (const uint32_t*)elp, out);
}

// round 15
// speedup vs baseline: 1.2637x; 1.1549x over previous
#include <cuda_runtime.h>
#include <cstdint>

#define N_SRC   100000
#define N_TGT   50000
#define N_EDGES 600000
#define CH      128
#define NREL    7
#define NTYP    4
#define NBINS   (N_TGT * NREL)          // 350000
#define NPART   342                     // ceil(NBINS/1024)
#define FCHUNK  28                      // NREL * 4

// Fused kernel tiling
#define TILE_M  64
#define ASTR    132                     // A row stride (words): 128 + 4 pad
#define A_BYTES (TILE_M * ASTR * 4)     // 33792 per buffer
#define BSTR    36                      // B row stride (words)
#define B_BYTES (128 * BSTR * 4)        // 18432 per stage
#define ELIST_CAP 1536

#define OFF_A0  0
#define OFF_A1  A_BYTES
#define OFF_B0  (2 * A_BYTES)
#define OFF_B1  (2 * A_BYTES + B_BYTES)
#define OFF_OFS (2 * A_BYTES + 2 * B_BYTES)
#define OFF_EL  (OFF_OFS + 452 * 4)
#define SMEM_TOTAL (OFF_EL + ELIST_CAP * 4)   // ~112.4KB -> 2 CTAs/SM

// Root kernel smem
#define RK_OFF_A   0
#define RK_OFF_B0  A_BYTES
#define RK_OFF_B1  (A_BYTES + B_BYTES)
#define RK_OFF_IDX (A_BYTES + 2 * B_BYTES)
#define RK_SMEM    (RK_OFF_IDX + 64 * 4)

// Scratch (allocation-free rule: __device__ globals).
// g_bincnt: zeroed at module load; fill_kernel's atomicSub drains it back to
// zero every invocation -> no memset needed (self-restoring invariant).
__device__ uint32_t g_bincnt[NBINS];
__device__ uint32_t g_binofs[NBINS + 1];
__device__ uint32_t g_part[NPART];
__device__ uint32_t g_elist[N_EDGES];
__device__ uint32_t g_wtf32[(NREL + NTYP) * CH * CH];
__device__ uint32_t g_tlist[NTYP * N_TGT];
__device__ uint32_t g_tcur[NTYP];       // zeroed by 16B memset each launch

// ---------------- helpers ----------------
__device__ __forceinline__ uint32_t to_tf32(float x) {
    uint32_t r;
    asm("cvt.rna.tf32.f32 %0, %1;" : "=r"(r) : "f"(x));
    return r;
}
__device__ __forceinline__ uint32_t smem_u32(const void* p) {
    uint32_t a;
    asm("{ .reg .u64 t; cvta.to.shared.u64 t, %1; cvt.u32.u64 %0, t; }" : "=r"(a) : "l"(p));
    return a;
}
__device__ __forceinline__ void cp16(uint32_t dst, const void* src, bool pred) {
    asm volatile("cp.async.ca.shared.global [%0], [%1], 16, %2;"
                 :: "r"(dst), "l"(src), "r"(pred ? 16 : 0) : "memory");
}
#define CP_COMMIT() asm volatile("cp.async.commit_group;" ::: "memory")
#define CP_WAIT(n)  asm volatile("cp.async.wait_group %0;" :: "n"(n) : "memory")
#define LDSM_X4(r0, r1, r2, r3, addr) \
    asm volatile("ldmatrix.sync.aligned.m8n8.x4.shared.b16 {%0,%1,%2,%3}, [%4];" \
        : "=r"(r0), "=r"(r1), "=r"(r2), "=r"(r3) : "r"(addr))

__device__ __forceinline__ void mma_tf32(float* c,
    uint32_t a0, uint32_t a1, uint32_t a2, uint32_t a3,
    uint32_t b0, uint32_t b1)
{
    asm volatile(
        "mma.sync.aligned.m16n8k8.row.col.f32.tf32.tf32.f32 "
        "{%0,%1,%2,%3}, {%4,%5,%6,%7}, {%8,%9}, {%0,%1,%2,%3};"
        : "+f"(c[0]), "+f"(c[1]), "+f"(c[2]), "+f"(c[3])
        : "r"(a0), "r"(a1), "r"(a2), "r"(a3), "r"(b0), "r"(b1));
}

// ---------------- CSR build ----------------
__global__ __launch_bounds__(256) void hist_kernel(
    const int* __restrict__ edst, const int* __restrict__ etyp,
    uint32_t* __restrict__ cnt)
{
    int e = blockIdx.x * 256 + threadIdx.x;
    if (e >= N_EDGES) return;
    atomicAdd(&cnt[__ldg(edst + e) * NREL + __ldg(etyp + e)], 1u);
}

__global__ __launch_bounds__(1024) void scanA_kernel(
    const uint32_t* __restrict__ cnt, uint32_t* __restrict__ part)
{
    __shared__ uint32_t s[1024];
    int t = threadIdx.x;
    int i = blockIdx.x * 1024 + t;
    s[t] = (i < NBINS) ? cnt[i] : 0u;
    __syncthreads();
    for (int off = 512; off; off >>= 1) {
        if (t < off) s[t] += s[t + off];
        __syncthreads();
    }
    if (t == 0) part[blockIdx.x] = s[0];
}

__global__ __launch_bounds__(1024) void scanC2_kernel(
    const uint32_t* __restrict__ cnt, const uint32_t* __restrict__ part,
    uint32_t* __restrict__ ofs)
{
    __shared__ uint32_t s[1024];
    __shared__ uint32_t sp[1024];
    __shared__ uint32_t blockPrefix;
    int t = threadIdx.x;
    int b = blockIdx.x;
    uint32_t p = 0;
    for (int i = t; i < b; i += 1024) p += part[i];
    sp[t] = p;
    __syncthreads();
    for (int off = 512; off; off >>= 1) {
        if (t < off) sp[t] += sp[t + off];
        __syncthreads();
    }
    if (t == 0) blockPrefix = sp[0];
    int i = b * 1024 + t;
    uint32_t v = (i < NBINS) ? cnt[i] : 0u;
    s[t] = v;
    __syncthreads();
    for (int off = 1; off < 1024; off <<= 1) {
        uint32_t x = (t >= off) ? s[t - off] : 0u;
        __syncthreads();
        s[t] += x;
        __syncthreads();
    }
    if (i < NBINS) ofs[i] = s[t] - v + blockPrefix;
    if (b == 0 && t == 0) ofs[NBINS] = N_EDGES;
}

__global__ __launch_bounds__(256) void fill_kernel(
    const int* __restrict__ esrc, const int* __restrict__ edst,
    const int* __restrict__ etyp,
    const uint32_t* __restrict__ ofs, uint32_t* __restrict__ cnt,
    uint32_t* __restrict__ elist)
{
    int e = blockIdx.x * 256 + threadIdx.x;
    if (e >= N_EDGES) return;
    int bin = __ldg(edst + e) * NREL + __ldg(etyp + e);
    uint32_t idx = atomicSub(&cnt[bin], 1u) - 1u;
    elist[ofs[bin] + idx] = (uint32_t)__ldg(esrc + e);
}

// ---------------- weight pre-convert (11 mats: 7 rel + 4 root) ------------
__global__ __launch_bounds__(256) void prep_weights(
    const float* __restrict__ relw, const float* __restrict__ rootw,
    uint32_t* __restrict__ wt)
{
    int i = blockIdx.x * 256 + threadIdx.x;
    const int NREL4 = NREL * CH * CH / 4;
    const int TOT4  = (NREL + NTYP) * CH * CH / 4;
    if (i >= TOT4) return;
    float4 v = (i < NREL4) ? ((const float4*)relw)[i]
                           : ((const float4*)rootw)[i - NREL4];
    uint4 w;
    w.x = to_tf32(v.x); w.y = to_tf32(v.y);
    w.z = to_tf32(v.z); w.w = to_tf32(v.w);
    ((uint4*)wt)[i] = w;
}

// ---------------- type classify: 4 per-type row lists ----------------
__global__ __launch_bounds__(256) void tclass_kernel(
    const int* __restrict__ ttype, uint32_t* __restrict__ tlist,
    uint32_t* __restrict__ tcur)
{
    __shared__ uint32_t cnt4[NTYP], base4[NTYP];
    int tid = threadIdx.x;
    int g = blockIdx.x * 256 + tid;
    if (tid < NTYP) cnt4[tid] = 0;
    __syncthreads();
    int t = -1; uint32_t rank = 0;
    if (g < N_TGT) { t = __ldg(ttype + g); rank = atomicAdd(&cnt4[t], 1u); }
    __syncthreads();
    if (tid < NTYP) base4[tid] = atomicAdd(&tcur[tid], cnt4[tid]);
    __syncthreads();
    if (t >= 0) tlist[t * N_TGT + base4[t] + rank] = (uint32_t)g;
}

// ---------------- root GEMM: out = x_target @ root_w[type]^T + root_b -----
// One type per CTA (64 rows from its list); K=128 = 4 chunks.
__global__ __launch_bounds__(256, 2) void root_kernel(
    const float* __restrict__ xt, const uint32_t* __restrict__ wt,
    const float* __restrict__ rootb,
    const uint32_t* __restrict__ tlist, const uint32_t* __restrict__ tcur,
    float* __restrict__ out)
{
    extern __shared__ char smc[];
    const uint32_t sb = smem_u32(smc);
    uint32_t* sIdx = (uint32_t*)(smc + RK_OFF_IDX);
    const int tid = threadIdx.x;
    const int wid = tid >> 5;
    const int lid = tid & 31;
    const int wm = wid & 1;
    const int wn = wid >> 1;

    // block -> (type, local 64-row block)
    int b = blockIdx.x, t = -1, lo = 0, accb = 0;
    uint32_t cnt_t = 0;
#pragma unroll
    for (int k = 0; k < NTYP; ++k) {
        uint32_t ck = tcur[k];
        int nb = (int)((ck + 63) >> 6);
        if (t < 0 && b < accb + nb) { t = k; lo = b - accb; cnt_t = ck; }
        accb += nb;
    }
    if (t < 0) return;
    int base = lo << 6;
    if (tid < 64)
        sIdx[tid] = ((uint32_t)(base + tid) < cnt_t)
                  ? tlist[t * N_TGT + base + tid] : 0xFFFFFFFFu;
    __syncthreads();

    // A: 64 rows x 32 float4 via cp.async
#pragma unroll
    for (int j = 0; j < 8; ++j) {
        int i = tid + (j << 8);
        int row = i >> 5, kv = i & 31;
        uint32_t g = sIdx[row];
        bool ok = (g != 0xFFFFFFFFu);
        cp16(sb + RK_OFF_A + row * (ASTR * 4) + (kv << 4),
             xt + ((size_t)(ok ? g : 0) << 7) + (kv << 2), ok);
    }
    CP_COMMIT();

    auto issueB = [&](int c) {
        const uint32_t* wsrc = wt + (((size_t)(NREL + t)) << 14) + (c << 5);
        uint32_t bB = sb + ((c & 1) ? RK_OFF_B1 : RK_OFF_B0);
#pragma unroll
        for (int j = 0; j < 4; ++j) {
            int i = tid + (j << 8);
            int cc = i >> 3, kv = i & 7;
            cp16(bB + cc * (BSTR * 4) + (kv << 4), wsrc + (cc << 7) + (kv << 2), true);
        }
    };
    issueB(0); CP_COMMIT();
    issueB(1); CP_COMMIT();

    float acc[2][4][4];
#pragma unroll
    for (int mi = 0; mi < 2; ++mi)
#pragma unroll
        for (int ni = 0; ni < 4; ++ni)
#pragma unroll
            for (int q = 0; q < 4; ++q) acc[mi][ni][q] = 0.0f;

    const uint32_t laneA = (uint32_t)((((wm << 5) + (lid & 15)) * (ASTR * 4))
                                      + ((lid >> 4) << 4));
    const uint32_t laneB = (uint32_t)((((wn << 5) + ((lid >> 4) << 3) + (lid & 7)) * (BSTR * 4))
                                      + (((lid >> 3) & 1) << 4));
    const uint32_t MI_OFF = 16u * ASTR * 4;
    const uint32_t NI_OFF = 16u * BSTR * 4;

    for (int c = 0; c < 4; ++c) {
        CP_WAIT(1);
        __syncthreads();
        const uint32_t aC = sb + RK_OFF_A + laneA + ((uint32_t)c << 7);
        const uint32_t bA = sb + ((c & 1) ? RK_OFF_B1 : RK_OFF_B0) + laneB;
#pragma unroll
        for (int ks = 0; ks < 4; ++ks) {
            const uint32_t ko = (uint32_t)(ks << 5);
            uint32_t a0[4], a1[4], b01[4], b23[4];
            LDSM_X4(a0[0], a0[1], a0[2], a0[3], aC + ko);
            LDSM_X4(a1[0], a1[1], a1[2], a1[3], aC + MI_OFF + ko);
            LDSM_X4(b01[0], b01[1], b01[2], b01[3], bA + ko);
            LDSM_X4(b23[0], b23[1], b23[2], b23[3], bA + NI_OFF + ko);
            mma_tf32(acc[0][0], a0[0], a0[1], a0[2], a0[3], b01[0], b01[1]);
            mma_tf32(acc[0][1], a0[0], a0[1], a0[2], a0[3], b01[2], b01[3]);
            mma_tf32(acc[0][2], a0[0], a0[1], a0[2], a0[3], b23[0], b23[1]);
            mma_tf32(acc[0][3], a0[0], a0[1], a0[2], a0[3], b23[2], b23[3]);
            mma_tf32(acc[1][0], a1[0], a1[1], a1[2], a1[3], b01[0], b01[1]);
            mma_tf32(acc[1][1], a1[0], a1[1], a1[2], a1[3], b01[2], b01[3]);
            mma_tf32(acc[1][2], a1[0], a1[1], a1[2], a1[3], b23[0], b23[1]);
            mma_tf32(acc[1][3], a1[0], a1[1], a1[2], a1[3], b23[2], b23[3]);
        }
        __syncthreads();
        if (c + 2 < 4) issueB(c + 2);
        CP_COMMIT();
    }

    // epilogue: out = acc + bias (first writer of out)
#pragma unroll
    for (int mi = 0; mi < 2; ++mi) {
#pragma unroll
        for (int half = 0; half < 2; ++half) {
            int row = (wm << 5) + (mi << 4) + (half << 3) + (lid >> 2);
            uint32_t g = sIdx[row];
            if (g == 0xFFFFFFFFu) continue;
#pragma unroll
            for (int ni = 0; ni < 4; ++ni) {
                int col = (wn << 5) + (ni << 3) + ((lid & 3) << 1);
                float2 o;
                o.x = acc[mi][ni][half * 2 + 0] + rootb[(t << 7) + col];
                o.y = acc[mi][ni][half * 2 + 1] + rootb[(t << 7) + col + 1];
                *(float2*)(out + ((size_t)g << 7) + col) = o;
            }
        }
    }
}

// ---------------- fused aggregate+GEMM (relations only, 28 chunks) --------
__global__ __launch_bounds__(256, 2) void fused_kernel(
    const float* __restrict__ xs, const uint32_t* __restrict__ wt,
    const uint32_t* __restrict__ binofs, const uint32_t* __restrict__ elist,
    float* __restrict__ out)
{
    extern __shared__ char smc[];
    const uint32_t sb = smem_u32(smc);
    uint32_t* sOfs = (uint32_t*)(smc + OFF_OFS);
    uint32_t* sEl  = (uint32_t*)(smc + OFF_EL);

    const int tid = threadIdx.x;
    const int wid = tid >> 5;
    const int lid = tid & 31;
    const int wm = wid & 1;
    const int wn = wid >> 1;
    const int row0 = blockIdx.x * TILE_M;

    for (int i = tid; i < 449; i += 256) {
        int idx = row0 * NREL + i;
        if (idx > NBINS) idx = NBINS;
        sOfs[i] = binofs[idx];
    }
    __syncthreads();
    const uint32_t e0 = sOfs[0];
    const int nEdge = (int)(sOfs[448] - e0);
    const bool useS = (nEdge <= ELIST_CAP);
    if (useS)
        for (int i = tid; i < nEdge; i += 256) sEl[i] = elist[e0 + i];
    __syncthreads();

    auto issueB = [&](int ci) {
        int seg = ci >> 2, k0 = (ci & 3) << 5;
        const uint32_t* wsrc = wt + ((size_t)seg << 14) + k0;
        uint32_t bB = sb + ((ci & 1) ? OFF_B1 : OFF_B0);
#pragma unroll
        for (int j = 0; j < 4; ++j) {
            int i = tid + (j << 8);
            int c = i >> 3, kv = i & 7;
            cp16(bB + c * (BSTR * 4) + (kv << 4), wsrc + (c << 7) + (kv << 2), true);
        }
    };

    auto buildA = [&](int seg, int buf) {
        uint32_t aB = sb + (buf ? OFF_A1 : OFF_A0);
#pragma unroll 2
        for (int rr = 0; rr < 8; ++rr) {
            int row = (wid << 3) + rr;
            int g = row0 + row;
            float4 a = make_float4(0.f, 0.f, 0.f, 0.f);
            if (g < N_TGT) {
                uint32_t beg = sOfs[row * NREL + seg];
                uint32_t end = sOfs[row * NREL + seg + 1];
                if (useS) {
                    for (uint32_t e = beg; e < end; ++e) {
                        uint32_t s = sEl[e - e0];
                        float4 v = ((const float4*)(xs + ((size_t)s << 7)))[lid];
                        a.x += v.x; a.y += v.y; a.z += v.z; a.w += v.w;
                    }
                } else {
                    for (uint32_t e = beg; e < end; ++e) {
                        uint32_t s = __ldg(elist + e);
                        float4 v = ((const float4*)(xs + ((size_t)s << 7)))[lid];
                        a.x += v.x; a.y += v.y; a.z += v.z; a.w += v.w;
                    }
                }
                float inv = 1.0f / fmaxf((float)(int)(end - beg), 1.0f);
                a.x *= inv; a.y *= inv; a.z *= inv; a.w *= inv;
            }
            asm volatile("st.shared.v4.b32 [%0], {%1,%2,%3,%4};"
                :: "r"(aB + row * (ASTR * 4) + (lid << 4)),
                   "f"(a.x), "f"(a.y), "f"(a.z), "f"(a.w) : "memory");
        }
    };

    float acc[2][4][4];
#pragma unroll
    for (int mi = 0; mi < 2; ++mi)
#pragma unroll
        for (int ni = 0; ni < 4; ++ni)
#pragma unroll
            for (int q = 0; q < 4; ++q) acc[mi][ni][q] = 0.0f;

    issueB(0); CP_COMMIT();
    issueB(1); CP_COMMIT();
    buildA(0, 0);

    const uint32_t laneA = (uint32_t)((((wm << 5) + (lid & 15)) * (ASTR * 4))
                                      + ((lid >> 4) << 4));
    const uint32_t laneB = (uint32_t)((((wn << 5) + ((lid >> 4) << 3) + (lid & 7)) * (BSTR * 4))
                                      + (((lid >> 3) & 1) << 4));
    const uint32_t MI_OFF = 16u * ASTR * 4;
    const uint32_t NI_OFF = 16u * BSTR * 4;

    for (int seg = 0; seg < NREL; ++seg) {
        int buf = seg & 1;
        if (seg + 1 < NREL) buildA(seg + 1, buf ^ 1);
        const uint32_t aA = sb + (buf ? OFF_A1 : OFF_A0) + laneA;
#pragma unroll
        for (int c = 0; c < 4; ++c) {
            int ci = (seg << 2) + c;
            CP_WAIT(1);
            __syncthreads();
            const uint32_t aC = aA + ((uint32_t)c << 7);
            const uint32_t bA = sb + ((ci & 1) ? OFF_B1 : OFF_B0) + laneB;
#pragma unroll
            for (int ks = 0; ks < 4; ++ks) {
                const uint32_t ko = (uint32_t)(ks << 5);
                uint32_t a0[4], a1[4], b01[4], b23[4];
                LDSM_X4(a0[0], a0[1], a0[2], a0[3], aC + ko);
                LDSM_X4(a1[0], a1[1], a1[2], a1[3], aC + MI_OFF + ko);
                LDSM_X4(b01[0], b01[1], b01[2], b01[3], bA + ko);
                LDSM_X4(b23[0], b23[1], b23[2], b23[3], bA + NI_OFF + ko);
                mma_tf32(acc[0][0], a0[0], a0[1], a0[2], a0[3], b01[0], b01[1]);
                mma_tf32(acc[0][1], a0[0], a0[1], a0[2], a0[3], b01[2], b01[3]);
                mma_tf32(acc[0][2], a0[0], a0[1], a0[2], a0[3], b23[0], b23[1]);
                mma_tf32(acc[0][3], a0[0], a0[1], a0[2], a0[3], b23[2], b23[3]);
                mma_tf32(acc[1][0], a1[0], a1[1], a1[2], a1[3], b01[0], b01[1]);
                mma_tf32(acc[1][1], a1[0], a1[1], a1[2], a1[3], b01[2], b01[3]);
                mma_tf32(acc[1][2], a1[0], a1[1], a1[2], a1[3], b23[0], b23[1]);
                mma_tf32(acc[1][3], a1[0], a1[1], a1[2], a1[3], b23[2], b23[3]);
            }
            __syncthreads();
            if (ci + 2 < FCHUNK) issueB(ci + 2);
            CP_COMMIT();
        }
    }

    // epilogue: out[g] += acc (root kernel wrote root + bias earlier)
#pragma unroll
    for (int mi = 0; mi < 2; ++mi) {
#pragma unroll
        for (int half = 0; half < 2; ++half) {
            int row = (wm << 5) + (mi << 4) + (half << 3) + (lid >> 2);
            int g = row0 + row;
            if (g >= N_TGT) continue;
#pragma unroll
            for (int ni = 0; ni < 4; ++ni) {
                int col = (wn << 5) + (ni << 3) + ((lid & 3) << 1);
                float2 o = *(float2*)(out + ((size_t)g << 7) + col);
                o.x += acc[mi][ni][half * 2 + 0];
                o.y += acc[mi][ni][half * 2 + 1];
                *(float2*)(out + ((size_t)g << 7) + col) = o;
            }
        }
    }
}

extern "C" void kernel_launch(void* const* d_in, const int* in_sizes, int n_in,
                              void* d_out, int out_size)
{
    const float* x_src  = (const float*)d_in[0];
    const float* x_tgt  = (const float*)d_in[1];
    const float* rel_w  = (const float*)d_in[2];
    const float* root_w = (const float*)d_in[3];
    const float* root_b = (const float*)d_in[4];
    const int*   e_src  = (const int*)d_in[5];
    const int*   e_dst  = (const int*)d_in[6];
    const int*   e_typ  = (const int*)d_in[7];
    const int*   n_typ  = (const int*)d_in[8];
    float* out = (float*)d_out;

    void *cntp, *ofsp, *partp, *elp, *wtp, *tlp, *tcp;
    cudaGetSymbolAddress(&cntp,  g_bincnt);
    cudaGetSymbolAddress(&ofsp,  g_binofs);
    cudaGetSymbolAddress(&partp, g_part);
    cudaGetSymbolAddress(&elp,   g_elist);
    cudaGetSymbolAddress(&wtp,   g_wtf32);
    cudaGetSymbolAddress(&tlp,   g_tlist);
    cudaGetSymbolAddress(&tcp,   g_tcur);

    cudaMemsetAsync(tcp, 0, NTYP * sizeof(uint32_t));
    hist_kernel<<<(N_EDGES + 255) / 256, 256>>>(e_dst, e_typ, (uint32_t*)cntp);
    scanA_kernel<<<NPART, 1024>>>((const uint32_t*)cntp, (uint32_t*)partp);
    scanC2_kernel<<<NPART, 1024>>>((const uint32_t*)cntp,
                                   (const uint32_t*)partp, (uint32_t*)ofsp);
    fill_kernel<<<(N_EDGES + 255) / 256, 256>>>(e_src, e_dst, e_typ,
                                                (const uint32_t*)ofsp,
                                                (uint32_t*)cntp, (uint32_t*)elp);
    prep_weights<<<((NREL + NTYP) * CH * CH / 4 + 255) / 256, 256>>>(
        rel_w, root_w, (uint32_t*)wtp);
    tclass_kernel<<<(N_TGT + 255) / 256, 256>>>(n_typ, (uint32_t*)tlp,
                                                (uint32_t*)tcp);

    cudaFuncSetAttribute(root_kernel,
                         cudaFuncAttributeMaxDynamicSharedMemorySize, RK_SMEM);
    root_kernel<<<N_TGT / 64 + NTYP + 1, 256, RK_SMEM>>>(
        x_tgt, (const uint32_t*)wtp, root_b,
        (const uint32_t*)tlp, (const uint32_t*)tcp, out);

    cudaFuncSetAttribute(fused_kernel,
                         cudaFuncAttributeMaxDynamicSharedMemorySize, SMEM_TOTAL);
    fused_kernel<<<(N_TGT + TILE_M - 1) / TILE_M, 256, SMEM_TOTAL>>>(
        x_src, (const uint32_t*)wtp,
        (const uint32_t*)ofsp, (const uint32_t*)elp, out);
}